// round 17
// baseline (speedup 1.0000x reference)
#include <cuda_runtime.h>
#include <cuda_fp16.h>

// PPISP pipeline. Round 17 = R16 (fused tables, best) + hoisted streaming
// prologue: the first two point-load sets are issued BEFORE the smem table
// build so their DRAM latency overlaps the build instead of following it.
// Build loop unrolled for MLP=4 on the param loads. Main loop unchanged.
//  - frame record 24B mixed: s_q {m00,m11,m22,h2(m01,m02)} + s_u 8B
//  - camera: s_Pa[j*4+c] = {h2(v0,v1), h2(p2,p3), h2(p4,mhd), a},
//    s_HC[c] = {h2(hc,hb) x3};  mhd = -d*0.5/c, hc = 0.5/c, hb = 0.5*b
//  - out = hb + hb*tanh(fma(xp, hc, mhd)),  xp = ex2(a*lg2(max(y,1e-6)))
//  launch_bounds(256,5): 51-reg cap, 40 warps/SM.

#define MAX_F 4096
#define LOG2E 1.44269504088896f
#define LN2   0.69314718055995f

__device__ __forceinline__ unsigned int f2h2(float a, float b) {
    __half2 h = __floats2half2_rn(a, b);
    return *reinterpret_cast<unsigned int*>(&h);
}
__device__ __forceinline__ float2 h22f2(unsigned int u) {
    __half2 h = *reinterpret_cast<__half2*>(&u);
    return __half22float2(h);
}

__device__ __forceinline__ float fast_lg2(float x) {
    float y; asm("lg2.approx.f32 %0, %1;" : "=f"(y) : "f"(x)); return y;
}
__device__ __forceinline__ float fast_ex2(float x) {
    float y; asm("ex2.approx.f32 %0, %1;" : "=f"(y) : "f"(x)); return y;
}
__device__ __forceinline__ float fast_tanh(float x) {
    float y; asm("tanh.approx.f32 %0, %1;" : "=f"(y) : "f"(x)); return y;
}
// softplus via MUFU: ln(1+e^x) = ln2 * lg2(1 + 2^(x*log2e)); err ~1e-7 here
__device__ __forceinline__ float softplus_fast(float x) {
    return LN2 * fast_lg2(1.0f + fast_ex2(x * LOG2E));
}

struct PtIn {
    float r, g, b, px, py;
    int c, f;
};

__device__ __forceinline__ PtIn load_pt(const float* __restrict__ rgb,
                                        const float* __restrict__ coords,
                                        const int* __restrict__ cam,
                                        const int* __restrict__ frm,
                                        int i)
{
    PtIn p;
    p.r  = __ldcs(rgb + 3 * i + 0);
    p.g  = __ldcs(rgb + 3 * i + 1);
    p.b  = __ldcs(rgb + 3 * i + 2);
    p.px = __ldcs(coords + 2 * i + 0);
    p.py = __ldcs(coords + 2 * i + 1);
    p.c  = __ldcs(cam + i);
    p.f  = __ldcs(frm + i);
    return p;
}

__global__ void __launch_bounds__(256, 5)
ppisp_main(const float* __restrict__ expo,
           const float* __restrict__ vig,
           const float* __restrict__ colp,
           const float* __restrict__ crf,
           const float* __restrict__ rgb,
           const float* __restrict__ coords,
           const int*   __restrict__ cam,
           const int*   __restrict__ frm,
           const int*   __restrict__ pW,
           const int*   __restrict__ pH,
           float* __restrict__ out,
           int B, int F)
{
    extern __shared__ float4 smbase[];
    float4* s_q  = smbase;                  // [F] 16B
    float4* s_Pa = s_q + F;                 // [12]
    float4* s_HC = s_Pa + 12;               // [4]
    uint2*  s_u  = (uint2*)(s_HC + 4);      // [F] 8B

    int stride = gridDim.x * blockDim.x;
    int i0 = blockIdx.x * blockDim.x + threadIdx.x;

    // ---- hoisted streaming prologue: overlap DRAM latency with table build ----
    PtIn a, b;
    bool has0 = (i0 < B);
    bool hasb = (i0 + stride < B);
    if (has0) a = load_pt(rgb, coords, cam, frm, i0);
    if (hasb) b = load_pt(rgb, coords, cam, frm, i0 + stride);

    // ---- build frame table in-block ----
#pragma unroll 4
    for (int f = threadIdx.x; f < F; f += 256) {
        float e = fast_ex2(__ldg(expo + f));
        const float4* cp4 = (const float4*)(colp + f * 8);
        float4 c0 = __ldg(cp4 + 0);     // {wb0, wb1, o0, o1}
        float4 c1 = __ldg(cp4 + 1);     // {o2, o3, o4, o5}
        float s0 = e * fast_ex2(c0.x * LOG2E);
        float s1 = e;
        float s2 = e * fast_ex2(c0.y * LOG2E);
        float o0 = c0.z, o1 = c0.w, o2 = c1.x;
        float o3 = c1.y, o4 = c1.z, o5 = c1.w;
        float m00 = (1.0f - o0 - o1) * s0, m01 = o0 * s1, m02 = o1 * s2;
        float m10 = o2 * s0, m11 = (1.0f - o2 - o3) * s1, m12 = o3 * s2;
        float m20 = o4 * s0, m21 = o5 * s1, m22 = (1.0f - o4 - o5) * s2;
        float4 q;
        q.x = m00; q.y = m11; q.z = m22;
        q.w = __uint_as_float(f2h2(m01, m02));
        s_q[f] = q;
        s_u[f] = make_uint2(f2h2(m10, m12), f2h2(m20, m21));
    }

    // ---- build camera tables in-block ----
    if (threadIdx.x < 12) {
        int c = threadIdx.x / 3;
        int j = threadIdx.x % 3;
        const float* vp = vig + c * 15 + j * 5;
        const float* kp = crf + c * 12 + j * 4;
        float av = softplus_fast(__ldg(kp + 0)) + 0.3f;
        float cc = softplus_fast(__ldg(kp + 2)) + 0.1f;
        float d  = __ldg(kp + 3);
        float hc  = 0.5f / cc;
        float mhd = -d * hc;
        float4 P;
        P.x = __uint_as_float(f2h2(__ldg(vp + 0), __ldg(vp + 1)));
        P.y = __uint_as_float(f2h2(__ldg(vp + 2), __ldg(vp + 3)));
        P.z = __uint_as_float(f2h2(__ldg(vp + 4), mhd));
        P.w = av;
        s_Pa[j * 4 + c] = P;
    }
    if (threadIdx.x < 4) {
        int c = threadIdx.x;
        const float* kp = crf + c * 12;
        float4 H; float* Hf = (float*)&H;
#pragma unroll
        for (int j = 0; j < 3; j++) {
            float bb = softplus_fast(__ldg(kp + 4 * j + 1)) + 0.3f;
            float cc = softplus_fast(__ldg(kp + 4 * j + 2)) + 0.1f;
            Hf[j] = __uint_as_float(f2h2(0.5f / cc, 0.5f * bb));
        }
        Hf[3] = 0.0f;
        s_HC[c] = H;
    }
    __syncthreads();

    if (!has0) return;

    float invW2 = 2.0f / (float)__ldg(pW);
    float invH2 = 2.0f / (float)__ldg(pH);

    int i = i0;

    // ---- R11 main loop: distance-2 rotating pipeline ----
    while (true) {
        bool hasc = (i + 2 * stride < B);
        PtIn cbuf;
        if (hasc) cbuf = load_pt(rgb, coords, cam, frm, i + 2 * stride);

        // ---- compute current point (a) ----
        {
            float u = fmaf(a.px, invW2, -1.0f);
            float v = fmaf(a.py, invH2, -1.0f);

            float rgbv[3] = {a.r, a.g, a.b};
            float t[3], aj[3], mhdj[3];
#pragma unroll
            for (int j = 0; j < 3; j++) {
                float4 P = s_Pa[j * 4 + a.c];
                float2 v01 = h22f2(__float_as_uint(P.x));
                float2 p23 = h22f2(__float_as_uint(P.y));
                float2 p4m = h22f2(__float_as_uint(P.z));
                float du = u - v01.x;
                float dv = v - v01.y;
                float r2 = fmaf(du, du, dv * dv);
                float gnv = fmaf(r2, fmaf(r2, fmaf(r2, p4m.x, p23.y), p23.x), 1.0f);
                t[j]    = rgbv[j] * gnv;
                aj[j]   = P.w;
                mhdj[j] = p4m.y;
            }

            float4 q  = s_q[a.f];
            uint2  uo = s_u[a.f];
            float2 m0102 = h22f2(__float_as_uint(q.w));
            float2 m1012 = h22f2(uo.x);
            float2 m2021 = h22f2(uo.y);

            float y0 = fmaf(q.x,     t[0], fmaf(m0102.x, t[1], m0102.y * t[2]));
            float y1 = fmaf(m1012.x, t[0], fmaf(q.y,     t[1], m1012.y * t[2]));
            float y2 = fmaf(m2021.x, t[0], fmaf(m2021.y, t[1], q.z     * t[2]));
            float yv[3] = {y0, y1, y2};

            float4 HC = s_HC[a.c];
            const float* Hf = (const float*)&HC;
#pragma unroll
            for (int j = 0; j < 3; j++) {
                float2 hcb = h22f2(__float_as_uint(Hf[j]));
                float xp  = fast_ex2(aj[j] * fast_lg2(fmaxf(yv[j], 1e-6f)));
                float arg = fmaf(xp, hcb.x, mhdj[j]);
                __stcs(out + 3 * i + j, fmaf(hcb.y, fast_tanh(arg), hcb.y));
            }
        }

        if (!hasb) break;
        a = b;
        b = cbuf;
        hasb = hasc;
        i += stride;
    }
}

extern "C" void kernel_launch(void* const* d_in, const int* in_sizes, int n_in,
                              void* d_out, int out_size) {
    const float* expo   = (const float*)d_in[0];
    const float* vig    = (const float*)d_in[1];
    const float* colp   = (const float*)d_in[2];
    const float* crf    = (const float*)d_in[3];
    const float* rgb    = (const float*)d_in[4];
    const float* coords = (const float*)d_in[5];
    const int*   cam    = (const int*)d_in[6];
    const int*   frm    = (const int*)d_in[7];
    const int*   pW     = (const int*)d_in[8];
    const int*   pH     = (const int*)d_in[9];
    float* out = (float*)d_out;

    int F = in_sizes[0];
    int B = in_sizes[6];
    if (F > MAX_F) F = MAX_F;   // table capacity guard (problem uses F=1000)

    // s_q[F] + s_Pa[12] + s_HC[4] + s_u[F]
    size_t shmem = (size_t)F * 16 + 16 * 16 + (size_t)F * 8;

    static bool attr_done = false;
    if (!attr_done) {
        cudaFuncSetAttribute(ppisp_main,
                             cudaFuncAttributeMaxDynamicSharedMemorySize,
                             (int)shmem > 49152 ? (int)shmem : 49152);
        attr_done = true;
    }

    int blocks = (B + 255) / 256;
    int maxb = 148 * 5;
    if (blocks > maxb) blocks = maxb;
    ppisp_main<<<blocks, 256, shmem>>>(expo, vig, colp, crf, rgb, coords,
                                       cam, frm, pW, pH, out, B, F);
}